// round 13
// baseline (speedup 1.0000x reference)
#include <cuda_runtime.h>
#include <math.h>

#define Bsz 64
#define Ssz 512
#define Hsz 400
#define Vsz 32000
#define Lsz 16
#define NPART 8
#define KC   50
#define JT   24
#define HC   8
#define HCW  50
#define LBLK 912          // loop kernel: 400 gemm + 512 score
#define GEMM_BLOCKS 400
#define SETUP_BLK 1184

// ---------------- device globals ----------------
__device__ float g_Gpart[NPART][Bsz][2400];
__device__ float g_hA[Bsz * Hsz];
__device__ float g_hB[Bsz * Hsz];
__device__ float g_x[Bsz * Hsz];
__device__ float g_xB[Lsz * Bsz * Hsz];
__device__ float g_giB[Lsz][Bsz][1200];
__device__ float g_encT[Bsz][Hsz][Ssz];
__device__ float g_scpart[2][HC][Bsz][Ssz];
__device__ int   g_cnt[2][Bsz];
// hierarchical counters (256B-strided sub lines)
__device__ int   g_subBar[37 * 64];
__device__ int   g_subGemm[Lsz][25 * 64];
__device__ int   g_subH[Lsz][8 * 64];
__device__ int   g_subF[Lsz][32 * 64];
__device__ int   g_barRoot, g_barFlag[8 * 64];
__device__ int   g_gemmRoot[Lsz], g_gemmFlag[Lsz][8 * 64];
__device__ int   g_hRoot[Lsz],    g_hFlag[Lsz][8 * 64];
__device__ int   g_fusedRoot[Lsz], g_fusedFlag[Lsz][8 * 64];

// ---------------- f32x2 helpers ----------------
__device__ __forceinline__ unsigned long long pk2(float x, float y) {
    unsigned long long r;
    asm("mov.b64 %0, {%1, %2};" : "=l"(r) : "f"(x), "f"(y));
    return r;
}
__device__ __forceinline__ void ffma2(unsigned long long& d,
                                      unsigned long long a, unsigned long long b) {
    asm("fma.rn.f32x2 %0, %1, %2, %0;" : "+l"(d) : "l"(a), "l"(b));
}
__device__ __forceinline__ float2 up2(unsigned long long v) {
    float2 f;
    asm("mov.b64 {%0, %1}, %2;" : "=f"(f.x), "=f"(f.y) : "l"(v));
    return f;
}

// ---------------- sync primitives (multi-line flags) ----------------
__device__ __forceinline__ void wait_flag_m(int* flagArr, int lane) {
    if (threadIdx.x == 0) {
        int v;
        int* p = &flagArr[lane * 64];
        while (true) {
            asm volatile("ld.acquire.gpu.b32 %0, [%1];" : "=r"(v) : "l"(p) : "memory");
            if (v) break;
            __nanosleep(32);
        }
    }
    __syncthreads();
}
__device__ __forceinline__ void set_flags(int* flagArr) {
    #pragma unroll
    for (int c = 0; c < 8; c++)
        asm volatile("st.release.gpu.b32 [%0], %1;" :: "l"(&flagArr[c * 64]), "r"(1) : "memory");
}
__device__ __forceinline__ void arrive_m(int* subs, int subIdx, int subTarget,
                                         int* root, int rootTarget, int* flagArr) {
    __threadfence();
    __syncthreads();
    if (threadIdx.x == 0) {
        int old = atomicAdd(&subs[subIdx * 64], 1);
        if (old == subTarget - 1) {
            int r = atomicAdd(root, 1);
            if (r == rootTarget - 1) set_flags(flagArr);
        }
    }
}

// ---------------- reset ----------------
__global__ __launch_bounds__(256) void reset_kernel() {
    int i = threadIdx.x;
    if (i < Lsz) {
        g_gemmRoot[i] = 0; g_hRoot[i] = 0; g_fusedRoot[i] = 0;
    }
    if (i == 0) g_barRoot = 0;
    if (i < Bsz) { g_cnt[0][i] = 0; g_cnt[1][i] = 0; }
    for (int k = i; k < 37; k += 256) g_subBar[k * 64] = 0;
    for (int k = i; k < Lsz * 25; k += 256) g_subGemm[k / 25][(k % 25) * 64] = 0;
    for (int k = i; k < Lsz * 8; k += 256)  g_subH[k >> 3][(k & 7) * 64] = 0;
    for (int k = i; k < Lsz * 32; k += 256) g_subF[k >> 5][(k & 31) * 64] = 0;
    for (int k = i; k < 8; k += 256) g_barFlag[k * 64] = 0;
    for (int k = i; k < Lsz * 8; k += 256) {
        g_gemmFlag[k >> 3][(k & 7) * 64] = 0;
        g_hFlag[k >> 3][(k & 7) * 64] = 0;
        g_fusedFlag[k >> 3][(k & 7) * 64] = 0;
    }
}

// ================= setup kernel: zero + init + xbuild | batch-gi + transpose =================
__global__ __launch_bounds__(256) void setup_kernel(
    const float* __restrict__ eh,
    const float* __restrict__ enc,
    const int* __restrict__ targets,
    const int* __restrict__ slot_p,
    const float* __restrict__ emb,
    const float* __restrict__ slot_emb,
    const float* __restrict__ Wih,
    float* __restrict__ out,
    int out_size)
{
    __shared__ float pool[4600];
    int bx = blockIdx.x;
    int tid = threadIdx.x;
    int gidx = bx * 256 + tid;
    const int nt = SETUP_BLK * 256;

    // ---- phase A: zero full output, init h/x, xbuild ----
    {
        int n4 = out_size / 4;
        for (int i = gidx; i < n4; i += nt) {
            float4* p = (float4*)out + i;
            asm volatile("st.global.cs.v4.f32 [%0], {%1, %2, %3, %4};"
                         :: "l"(p), "f"(0.f), "f"(0.f), "f"(0.f), "f"(0.f) : "memory");
        }
        for (int i = n4 * 4 + gidx; i < out_size; i += nt)
            asm volatile("st.global.cs.f32 [%0], %1;" :: "l"(out + i), "f"(0.f) : "memory");

        int slot = slot_p[0];
        for (int i = gidx; i < Bsz * Hsz; i += nt) {
            g_hA[i] = eh[i];
            g_x[i] = slot_emb[slot * Hsz + i % Hsz];
        }
        for (int i = gidx; i < Lsz * Bsz * 100; i += nt) {
            int row = i / 100, q = i % 100;
            int t = row >> 6, b = row & 63;
            const float* src = (t == 0) ? (slot_emb + slot * Hsz)
                                        : (emb + (size_t)targets[b * Lsz + (t - 1)] * Hsz);
            ((float4*)(g_xB + (size_t)row * Hsz))[q] = ((const float4*)src)[q];
        }
    }
    arrive_m(g_subBar, bx % 37, 32, &g_barRoot, 37, g_barFlag);
    wait_flag_m(g_barFlag, bx & 7);

    // ---- phase B ----
    if (bx < 960) {
        // batch-gi unit: bt = bx/60, jbase = (bx%60)*20 (20 j's, fine-grained)
        float (*As)[68] = (float(*)[68])pool;            // 50 x 68
        float (*Ws)[22] = (float(*)[22])(pool + 3400);   // 50 x 22
        int bt = bx / 60;
        int jbase = (bx % 60) * 20;
        const float* A = g_xB + (size_t)bt * Bsz * Hsz;
        int tj = tid / 16;       // 0..15 (active < 10)
        int tb = tid % 16;
        int b0 = 4 * tb;
        int j0 = 2 * tj;
        bool active = (tj < 10);

        unsigned long long acc[2][2];
        acc[0][0] = acc[0][1] = acc[1][0] = acc[1][1] = 0ULL;

        for (int kt = 0; kt < 8; kt++) {
            int kbase = kt * 50;
            __syncthreads();
            for (int i = tid; i < 1600; i += 256) {
                int q = i >> 6, b = i & 63;
                float2 v = *(const float2*)&A[b * Hsz + kbase + 2 * q];
                As[2 * q + 0][b] = v.x;
                As[2 * q + 1][b] = v.y;
            }
            for (int i = tid; i < 500; i += 256) {
                int q = i / 20, j = i % 20;
                float2 v = *(const float2*)&Wih[(size_t)(jbase + j) * Hsz + kbase + 2 * q];
                Ws[2 * q + 0][j] = v.x;
                Ws[2 * q + 1][j] = v.y;
            }
            __syncthreads();
            if (active) {
                #pragma unroll 5
                for (int k = 0; k < 50; k++) {
                    float4 av = *(const float4*)&As[k][b0];
                    float2 wv = *(const float2*)&Ws[k][j0];
                    unsigned long long a01 = pk2(av.x, av.y);
                    unsigned long long a23 = pk2(av.z, av.w);
                    ffma2(acc[0][0], a01, pk2(wv.x, wv.x)); ffma2(acc[0][1], a23, pk2(wv.x, wv.x));
                    ffma2(acc[1][0], a01, pk2(wv.y, wv.y)); ffma2(acc[1][1], a23, pk2(wv.y, wv.y));
                }
            }
        }
        if (active) {
            #pragma unroll
            for (int bb = 0; bb < 4; bb++) {
                float a0 = (bb & 1) ? up2(acc[0][bb >> 1]).y : up2(acc[0][bb >> 1]).x;
                float a1 = (bb & 1) ? up2(acc[1][bb >> 1]).y : up2(acc[1][bb >> 1]).x;
                *(float2*)&g_giB[bt][b0 + bb][jbase + j0] = make_float2(a0, a1);
            }
        }
    } else {
        // transpose enc[b][s][h] -> encT[b][h][s]
        float (*tile)[33] = (float(*)[33])pool;
        int tx = tid & 31, ty = tid >> 5;    // 32 x 8
        for (int tt = bx - 960; tt < Bsz * 16 * 13; tt += SETUP_BLK - 960) {
            int b = tt / (16 * 13);
            int rem = tt % (16 * 13);
            int s0 = (rem / 13) * 32;
            int h0 = (rem % 13) * 32;
            __syncthreads();
            #pragma unroll
            for (int i = 0; i < 32; i += 8) {
                int s = s0 + ty + i, h = h0 + tx;
                if (h < Hsz) tile[ty + i][tx] = enc[((size_t)b * Ssz + s) * Hsz + h];
            }
            __syncthreads();
            #pragma unroll
            for (int i = 0; i < 32; i += 8) {
                int h = h0 + ty + i, s = s0 + tx;
                if (h < Hsz) g_encT[b][h][s] = tile[tx][ty + i];
            }
        }
    }
}

// ================= loop kernel: 16-step recurrence =================
__global__ __launch_bounds__(128, 8) void loop_kernel(
    const int* __restrict__ lens,
    const int* __restrict__ uttrs,
    const int* __restrict__ targets,
    const int* __restrict__ use_tf_p,
    const float* __restrict__ emb,
    const float* __restrict__ Wih,
    const float* __restrict__ Whh,
    const float* __restrict__ bih,
    const float* __restrict__ bhh,
    float* __restrict__ out,
    int write_preds)
{
    __shared__ float pool[6700];
    int bx = blockIdx.x;
    int tid = threadIdx.x;
    int lane8 = bx & 7;
    int tf = use_tf_p[0];

    if (bx < GEMM_BLOCKS) {
        // -------- GEMM role (+ gates for bx<64); W persists in smem --------
        float (*As)[68]  = (float(*)[68])pool;
        float (*WhS)[28] = (float(*)[28])(pool + 3400);
        float (*WiS)[28] = (float(*)[28])(pool + 4800);
        int jt = bx >> 3, ks = bx & 7;
        int jbase = jt * JT;
        int kbase = ks * KC;
        int tj = tid / 16, tb = tid % 16;
        int b0 = 4 * tb, j0 = 4 * tj;
        bool active = (tj < 6);
        bool gates_duty = (bx < Bsz);
        int gb = bx;

        for (int i = tid; i < 600; i += 128) {
            int q = i / JT, j = i % JT;
            float2 v = *(const float2*)&Whh[(size_t)(jbase + j) * Hsz + kbase + 2 * q];
            WhS[2 * q + 0][j] = v.x;
            WhS[2 * q + 1][j] = v.y;
        }
        if (!tf) {
            for (int i = tid; i < 600; i += 128) {
                int q = i / JT, j = i % JT;
                float2 v = *(const float2*)&Wih[(size_t)(jbase + j) * Hsz + kbase + 2 * q];
                WiS[2 * q + 0][j] = v.x;
                WiS[2 * q + 1][j] = v.y;
            }
        }
        __syncthreads();

        for (int t = 0; t < Lsz; t++) {
            if (t > 0)
                wait_flag_m(tf ? g_hFlag[t - 1] : g_fusedFlag[t - 1], lane8);
            const float* hin = (t & 1) ? g_hB : g_hA;
            for (int mat = tf ? 1 : 0; mat < 2; mat++) {
                const float* A = mat ? hin : g_x;
                float (*Ws)[28] = mat ? WhS : WiS;
                __syncthreads();
                for (int i = tid; i < 1600; i += 128) {
                    int q = i >> 6, b = i & 63;
                    float2 v = *(const float2*)&A[b * Hsz + kbase + 2 * q];
                    As[2 * q + 0][b] = v.x;
                    As[2 * q + 1][b] = v.y;
                }
                __syncthreads();
                if (active) {
                    unsigned long long acc[4][2];
                    #pragma unroll
                    for (int jj = 0; jj < 4; jj++) { acc[jj][0] = 0ULL; acc[jj][1] = 0ULL; }
                    #pragma unroll 5
                    for (int k = 0; k < KC; k++) {
                        float4 av = *(const float4*)&As[k][b0];
                        float4 wv = *(const float4*)&Ws[k][j0];
                        unsigned long long a01 = pk2(av.x, av.y);
                        unsigned long long a23 = pk2(av.z, av.w);
                        unsigned long long w0 = pk2(wv.x, wv.x);
                        unsigned long long w1 = pk2(wv.y, wv.y);
                        unsigned long long w2 = pk2(wv.z, wv.z);
                        unsigned long long w3 = pk2(wv.w, wv.w);
                        ffma2(acc[0][0], a01, w0); ffma2(acc[0][1], a23, w0);
                        ffma2(acc[1][0], a01, w1); ffma2(acc[1][1], a23, w1);
                        ffma2(acc[2][0], a01, w2); ffma2(acc[2][1], a23, w2);
                        ffma2(acc[3][0], a01, w3); ffma2(acc[3][1], a23, w3);
                    }
                    int obase = mat * 1200 + jbase + j0;
                    #pragma unroll
                    for (int bb = 0; bb < 4; bb++) {
                        float v0 = (bb & 1) ? up2(acc[0][bb >> 1]).y : up2(acc[0][bb >> 1]).x;
                        float v1 = (bb & 1) ? up2(acc[1][bb >> 1]).y : up2(acc[1][bb >> 1]).x;
                        float v2 = (bb & 1) ? up2(acc[2][bb >> 1]).y : up2(acc[2][bb >> 1]).x;
                        float v3 = (bb & 1) ? up2(acc[3][bb >> 1]).y : up2(acc[3][bb >> 1]).x;
                        *(float4*)&g_Gpart[ks][b0 + bb][obase] = make_float4(v0, v1, v2, v3);
                    }
                }
            }
            arrive_m(g_subGemm[t], bx % 25, 16, &g_gemmRoot[t], 25, g_gemmFlag[t]);

            if (gates_duty) {
                wait_flag_m(g_gemmFlag[t], lane8);
                if (t >= 2) wait_flag_m(g_fusedFlag[t - 2], lane8);  // h(t-2) readers done
                const float* hprev = (t & 1) ? g_hB : g_hA;
                float*       hout  = (t & 1) ? g_hA : g_hB;
                for (int j = tid; j < Hsz; j += 128) {
                    float ir = bih[j], iz = bih[400 + j], in_ = bih[800 + j];
                    float hr = bhh[j], hz = bhh[400 + j], hn = bhh[800 + j];
                    if (tf) {
                        ir += g_giB[t][gb][j];
                        iz += g_giB[t][gb][400 + j];
                        in_ += g_giB[t][gb][800 + j];
                        #pragma unroll
                        for (int p = 0; p < NPART; p++) {
                            const float* P = &g_Gpart[p][gb][0];
                            hr += P[1200 + j]; hz += P[1600 + j]; hn += P[2000 + j];
                        }
                    } else {
                        #pragma unroll
                        for (int p = 0; p < NPART; p++) {
                            const float* P = &g_Gpart[p][gb][0];
                            ir += P[j];        iz += P[400 + j];  in_ += P[800 + j];
                            hr += P[1200 + j]; hz += P[1600 + j]; hn += P[2000 + j];
                        }
                    }
                    float r = 1.f / (1.f + expf(-(ir + hr)));
                    float z = 1.f / (1.f + expf(-(iz + hz)));
                    float n = tanhf(in_ + r * hn);
                    hout[gb * Hsz + j] = (1.f - z) * n + z * hprev[gb * Hsz + j];
                }
                arrive_m(g_subH[t], gb >> 3, 8, &g_hRoot[t], 8, g_hFlag[t]);
            }
        }
    } else {
        // -------- score role: scores + tail --------
        float* sh   = pool;                 // 64
        float* redv = pool + 64;            // 128
        int*   redi = (int*)(pool + 192);   // 128
        float* flg  = pool + 320;

        int fb = bx - GEMM_BLOCKS;
        int b  = fb >> 3;
        int hc = fb & 7;
        int len = lens[b];
        int sub = fb >> 4;   // 0..31, 16 per sub

        for (int t = 0; t < Lsz; t++) {
            int par = t & 1;
            if (t >= 2) wait_flag_m(g_fusedFlag[t - 2], lane8);
            wait_flag_m(g_hFlag[t], lane8);

            const float* hnew = (t & 1) ? g_hA : g_hB;
            if (tid < HCW)
                sh[tid] = hnew[b * Hsz + hc * HCW + tid];
            __syncthreads();

            int s0 = 4 * tid;
            if (s0 < len) {
                const float4* ep = (const float4*)&g_encT[b][hc * HCW][0] + tid;
                float4 acc = make_float4(0.f, 0.f, 0.f, 0.f);
                #pragma unroll 10
                for (int h = 0; h < HCW; h++) {
                    float hv = sh[h];
                    float4 e = ep[(size_t)h * 128];
                    acc.x += e.x * hv; acc.y += e.y * hv;
                    acc.z += e.z * hv; acc.w += e.w * hv;
                }
                *(float4*)&g_scpart[par][hc][b][s0] = acc;
            }

            __threadfence();
            __syncthreads();
            if (tid == 0) {
                int old = atomicAdd(&g_cnt[par][b], 1);
                flg[0] = (old == HC - 1) ? 1.f : 0.f;
            }
            __syncthreads();
            bool last = (flg[0] != 0.f);

            if (last) {
                __threadfence();
                if (tid == 0) g_cnt[par][b] = 0;

                float v[4];
                #pragma unroll
                for (int q = 0; q < 4; q++) {
                    int s = tid + 128 * q;
                    if (s < len) {
                        float sum = 0.f;
                        #pragma unroll
                        for (int p = 0; p < HC; p++) sum += g_scpart[par][p][b][s];
                        v[q] = sum;
                    } else {
                        v[q] = -INFINITY;
                    }
                }
                float mv = v[0]; int mi = tid;
                #pragma unroll
                for (int q = 1; q < 4; q++)
                    if (v[q] > mv) { mv = v[q]; mi = tid + 128 * q; }
                redv[tid] = mv;
                redi[tid] = mi;
                __syncthreads();
                for (int st = 64; st > 0; st >>= 1) {
                    if (tid < st) {
                        float w2 = redv[tid + st];
                        int   i2 = redi[tid + st];
                        if (w2 > redv[tid] || (w2 == redv[tid] && i2 < redi[tid])) {
                            redv[tid] = w2;
                            redi[tid] = i2;
                        }
                    }
                    __syncthreads();
                }
                float m = redv[0];
                int amax = redi[0];
                __syncthreads();

                float e[4], lsum = 0.f;
                #pragma unroll
                for (int q = 0; q < 4; q++) {
                    e[q] = expf(v[q] - m);
                    lsum += e[q];
                }
                redv[tid] = lsum;
                __syncthreads();
                for (int st = 64; st > 0; st >>= 1) {
                    if (tid < st) redv[tid] += redv[tid + st];
                    __syncthreads();
                }
                float inv = 1.f / redv[0];

                float* orow = out + (size_t)b * Lsz * Vsz + (size_t)t * Vsz;
                #pragma unroll
                for (int q = 0; q < 4; q++) {
                    int s = tid + 128 * q;
                    if (s < len)
                        atomicAdd(&orow[uttrs[b * Ssz + s]], e[q] * inv);
                }

                if (tid == 0) {
                    int pred = uttrs[b * Ssz + amax];
                    if (write_preds)
                        out[(size_t)Bsz * Lsz * Vsz + (size_t)t * Bsz + b] = (float)pred;
                    ((int*)flg)[1] = tf ? targets[b * Lsz + t] : pred;
                }
                __syncthreads();
                if (!tf) {
                    int nxt = ((int*)flg)[1];
                    if (tid < 100)
                        ((float4*)(g_x + b * Hsz))[tid] =
                            ((const float4*)(emb + (size_t)nxt * Hsz))[tid];
                }
            }

            arrive_m(g_subF[t], sub, 16, &g_fusedRoot[t], 32, g_fusedFlag[t]);
        }
    }
}

// ---------------- launch ----------------
extern "C" void kernel_launch(void* const* d_in, const int* in_sizes, int n_in,
                              void* d_out, int out_size) {
    const float* eh       = (const float*)d_in[0];
    const float* enc      = (const float*)d_in[1];
    const int*   lens     = (const int*)d_in[2];
    const int*   uttrs    = (const int*)d_in[3];
    const int*   targets  = (const int*)d_in[4];
    const int*   slot     = (const int*)d_in[5];
    const int*   use_tf   = (const int*)d_in[6];
    const float* emb      = (const float*)d_in[7];
    const float* slot_emb = (const float*)d_in[8];
    const float* Wih      = (const float*)d_in[9];
    const float* Whh      = (const float*)d_in[10];
    const float* bih      = (const float*)d_in[11];
    const float* bhh      = (const float*)d_in[12];
    float* out = (float*)d_out;

    int write_preds = out_size > Bsz * Lsz * Vsz;
    reset_kernel<<<1, 256>>>();
    setup_kernel<<<SETUP_BLK, 256>>>(eh, enc, targets, slot, emb, slot_emb, Wih,
                                     out, out_size);
    loop_kernel<<<LBLK, 128>>>(lens, uttrs, targets, use_tf, emb, Wih, Whh,
                               bih, bhh, out, write_preds);
}

// round 15
// speedup vs baseline: 1.0475x; 1.0475x over previous
#include <cuda_runtime.h>
#include <math.h>

#define Bsz 64
#define Ssz 512
#define Hsz 400
#define Vsz 32000
#define Lsz 16
#define NPART 8
#define KC   50
#define JT   24
#define HC   8
#define HCW  50
#define NBLK 912
#define GEMM_BLOCKS 400
#define BH   (Bsz * Hsz)

// ---------------- data globals ----------------
__device__ float g_Gpart[NPART][Bsz][2400];
__device__ float g_hHist[Lsz + 1][BH];
__device__ float g_x[BH];
__device__ float g_xB[Lsz * BH];
__device__ float g_giB[Lsz][Bsz][1200];
__device__ float g_encT[Bsz][Hsz][Ssz];
__device__ float g_scpartL[Lsz][HC][Bsz][Ssz];   // 16-deep: no reuse hazards

// ---------------- sync state ----------------
// phase-0 barrier (armed by reset_kernel); 912 = 38 groups x 24
__device__ int g_subBar[38 * 64];
__device__ int g_barRoot, g_barFlag[8 * 64];
// loop sync (zeroed in phase 0 each replay)
#define SYNC_WORDS (16*25*64 + 16 + 16*8*64 + 17*8*64 + 17 + 17*8*64 + 16 + 16*8*64 \
                    + 32*64 + 1 + 8*64 + 16*64 + 16 + 16*8*64)
__device__ int g_sync[SYNC_WORDS];
#define OFF_SUBGEMM   0
#define OFF_GEMMROOT  (OFF_SUBGEMM + 16*25*64)
#define OFF_GEMMFLAG  (OFF_GEMMROOT + 16)
#define OFF_SUBH      (OFF_GEMMFLAG + 16*8*64)
#define OFF_HROOT     (OFF_SUBH + 17*8*64)
#define OFF_HFLAG     (OFF_HROOT + 17)
#define OFF_BATCHCNT  (OFF_HFLAG + 17*8*64)
#define OFF_BATCHFLAG (OFF_BATCHCNT + 16)
#define OFF_TSUB      (OFF_BATCHFLAG + 16*8*64)
#define OFF_TROOT     (OFF_TSUB + 32*64)
#define OFF_TFLAG     (OFF_TROOT + 1)
#define OFF_CNTBT     (OFF_TFLAG + 8*64)
#define OFF_FUSEDCNT  (OFF_CNTBT + 16*64)
#define OFF_FUSEDFLAG (OFF_FUSEDCNT + 16)

// ---------------- f32x2 helpers ----------------
__device__ __forceinline__ unsigned long long pk2(float x, float y) {
    unsigned long long r;
    asm("mov.b64 %0, {%1, %2};" : "=l"(r) : "f"(x), "f"(y));
    return r;
}
__device__ __forceinline__ void ffma2(unsigned long long& d,
                                      unsigned long long a, unsigned long long b) {
    asm("fma.rn.f32x2 %0, %1, %2, %0;" : "+l"(d) : "l"(a), "l"(b));
}
__device__ __forceinline__ float2 up2(unsigned long long v) {
    float2 f;
    asm("mov.b64 {%0, %1}, %2;" : "=f"(f.x), "=f"(f.y) : "l"(v));
    return f;
}

// ---------------- sync primitives ----------------
__device__ __forceinline__ void wait_flag_m(int* flagArr, int lane) {
    if (threadIdx.x == 0) {
        int v;
        int* p = &flagArr[lane * 64];
        while (true) {
            asm volatile("ld.acquire.gpu.b32 %0, [%1];" : "=r"(v) : "l"(p) : "memory");
            if (v) break;
            __nanosleep(32);
        }
    }
    __syncthreads();
}
__device__ __forceinline__ void set_flags(int* flagArr) {
    #pragma unroll
    for (int c = 0; c < 8; c++)
        asm volatile("st.release.gpu.b32 [%0], %1;" :: "l"(&flagArr[c * 64]), "r"(1) : "memory");
}
__device__ __forceinline__ void arrive_m(int* subs, int subIdx, int subTarget,
                                         int* root, int rootTarget, int* flagArr) {
    __threadfence();
    __syncthreads();
    if (threadIdx.x == 0) {
        int old = atomicAdd(&subs[subIdx * 64], 1);
        if (old == subTarget - 1) {
            int r = atomicAdd(root, 1);
            if (r == rootTarget - 1) set_flags(flagArr);
        }
    }
}

// ---------------- reset: arm only the phase-0 barrier ----------------
__global__ __launch_bounds__(256) void reset_kernel() {
    int i = threadIdx.x;
    for (int k = i; k < 38 * 64; k += 256) g_subBar[k] = 0;
    for (int k = i; k < 8 * 64; k += 256) g_barFlag[k] = 0;
    if (i == 0) g_barRoot = 0;
}

// ================= persistent kernel =================
__global__ __launch_bounds__(128, 8) void persist_kernel(
    const float* __restrict__ eh,
    const float* __restrict__ enc,
    const int* __restrict__ lens,
    const int* __restrict__ uttrs,
    const int* __restrict__ targets,
    const int* __restrict__ slot_p,
    const int* __restrict__ use_tf_p,
    const float* __restrict__ emb,
    const float* __restrict__ slot_emb,
    const float* __restrict__ Wih,
    const float* __restrict__ Whh,
    const float* __restrict__ bih,
    const float* __restrict__ bhh,
    float* __restrict__ out,
    int out_size, int write_preds)
{
    __shared__ float pool[6700];
    int bx = blockIdx.x;
    int tid = threadIdx.x;
    int gidx = bx * 128 + tid;
    const int nt = NBLK * 128;
    int lane8 = bx & 7;

    // ============ Phase 0: zero sync + preds pad, init h0/x, xbuild ============
    {
        for (int i = gidx; i < SYNC_WORDS; i += nt) g_sync[i] = 0;
        for (int i = (Bsz * Lsz * Vsz) + gidx; i < out_size; i += nt)
            out[i] = 0.f;
        int slot = slot_p[0];
        for (int i = gidx; i < BH; i += nt) {
            g_hHist[0][i] = eh[i];
            g_x[i] = slot_emb[slot * Hsz + i % Hsz];
        }
        for (int i = gidx; i < Lsz * Bsz * 100; i += nt) {
            int row = i / 100, q = i % 100;
            int t = row >> 6, b = row & 63;
            const float* src = (t == 0) ? (slot_emb + slot * Hsz)
                                        : (emb + (size_t)targets[b * Lsz + (t - 1)] * Hsz);
            ((float4*)(g_xB + (size_t)row * Hsz))[q] = ((const float4*)src)[q];
        }
    }
    arrive_m(g_subBar, bx % 38, 24, &g_barRoot, 38, g_barFlag);   // 912 = 38 x 24
    wait_flag_m(g_barFlag, lane8);

    int tf = use_tf_p[0];

    if (bx < GEMM_BLOCKS) {
        // ================= recurrence chain: gemm (+ gates for bx<64) =================
        float (*As)[68]  = (float(*)[68])pool;
        float (*WhS)[28] = (float(*)[28])(pool + 3400);
        float (*WiS)[28] = (float(*)[28])(pool + 4800);
        int jt = bx >> 3, ks = bx & 7;
        int jbase = jt * JT;
        int kbase = ks * KC;
        int tj = tid / 16, tb = tid % 16;
        int b0 = 4 * tb, j0 = 4 * tj;
        bool active = (tj < 6);
        bool gates_duty = (bx < Bsz);
        int gb = bx;

        for (int i = tid; i < 600; i += 128) {
            int q = i / JT, j = i % JT;
            float2 v = *(const float2*)&Whh[(size_t)(jbase + j) * Hsz + kbase + 2 * q];
            WhS[2 * q + 0][j] = v.x;
            WhS[2 * q + 1][j] = v.y;
        }
        if (!tf) {
            for (int i = tid; i < 600; i += 128) {
                int q = i / JT, j = i % JT;
                float2 v = *(const float2*)&Wih[(size_t)(jbase + j) * Hsz + kbase + 2 * q];
                WiS[2 * q + 0][j] = v.x;
                WiS[2 * q + 1][j] = v.y;
            }
        }
        __syncthreads();

        for (int t = 0; t < Lsz; t++) {
            if (t > 0) wait_flag_m(&g_sync[OFF_HFLAG + t * 8 * 64], lane8);
            if (!tf && t > 0) wait_flag_m(&g_sync[OFF_FUSEDFLAG + (t - 1) * 8 * 64], lane8);
            const float* hin = g_hHist[t];
            for (int mat = tf ? 1 : 0; mat < 2; mat++) {
                const float* A = mat ? hin : g_x;
                float (*Ws)[28] = mat ? WhS : WiS;
                __syncthreads();
                for (int i = tid; i < 1600; i += 128) {
                    int q = i >> 6, b = i & 63;
                    float2 v = *(const float2*)&A[b * Hsz + kbase + 2 * q];
                    As[2 * q + 0][b] = v.x;
                    As[2 * q + 1][b] = v.y;
                }
                __syncthreads();
                if (active) {
                    unsigned long long acc[4][2];
                    #pragma unroll
                    for (int jj = 0; jj < 4; jj++) { acc[jj][0] = 0ULL; acc[jj][1] = 0ULL; }
                    #pragma unroll 5
                    for (int k = 0; k < KC; k++) {
                        float4 av = *(const float4*)&As[k][b0];
                        float4 wv = *(const float4*)&Ws[k][j0];
                        unsigned long long a01 = pk2(av.x, av.y);
                        unsigned long long a23 = pk2(av.z, av.w);
                        unsigned long long w0 = pk2(wv.x, wv.x);
                        unsigned long long w1 = pk2(wv.y, wv.y);
                        unsigned long long w2 = pk2(wv.z, wv.z);
                        unsigned long long w3 = pk2(wv.w, wv.w);
                        ffma2(acc[0][0], a01, w0); ffma2(acc[0][1], a23, w0);
                        ffma2(acc[1][0], a01, w1); ffma2(acc[1][1], a23, w1);
                        ffma2(acc[2][0], a01, w2); ffma2(acc[2][1], a23, w2);
                        ffma2(acc[3][0], a01, w3); ffma2(acc[3][1], a23, w3);
                    }
                    int obase = mat * 1200 + jbase + j0;
                    #pragma unroll
                    for (int bb = 0; bb < 4; bb++) {
                        float v0 = (bb & 1) ? up2(acc[0][bb >> 1]).y : up2(acc[0][bb >> 1]).x;
                        float v1 = (bb & 1) ? up2(acc[1][bb >> 1]).y : up2(acc[1][bb >> 1]).x;
                        float v2 = (bb & 1) ? up2(acc[2][bb >> 1]).y : up2(acc[2][bb >> 1]).x;
                        float v3 = (bb & 1) ? up2(acc[3][bb >> 1]).y : up2(acc[3][bb >> 1]).x;
                        *(float4*)&g_Gpart[ks][b0 + bb][obase] = make_float4(v0, v1, v2, v3);
                    }
                }
            }
            arrive_m(&g_sync[OFF_SUBGEMM + t * 25 * 64], bx % 25, 16,
                     &g_sync[OFF_GEMMROOT + t], 25, &g_sync[OFF_GEMMFLAG + t * 8 * 64]);

            if (gates_duty) {
                wait_flag_m(&g_sync[OFF_GEMMFLAG + t * 8 * 64], lane8);
                if (tf) wait_flag_m(&g_sync[OFF_BATCHFLAG + t * 8 * 64], lane8);
                const float* hprev = g_hHist[t];
                float*       hout  = g_hHist[t + 1];
                for (int j = tid; j < Hsz; j += 128) {
                    float ir = bih[j], iz = bih[400 + j], in_ = bih[800 + j];
                    float hr = bhh[j], hz = bhh[400 + j], hn = bhh[800 + j];
                    if (tf) {
                        ir += g_giB[t][gb][j];
                        iz += g_giB[t][gb][400 + j];
                        in_ += g_giB[t][gb][800 + j];
                        #pragma unroll
                        for (int p = 0; p < NPART; p++) {
                            const float* P = &g_Gpart[p][gb][0];
                            hr += P[1200 + j]; hz += P[1600 + j]; hn += P[2000 + j];
                        }
                    } else {
                        #pragma unroll
                        for (int p = 0; p < NPART; p++) {
                            const float* P = &g_Gpart[p][gb][0];
                            ir += P[j];        iz += P[400 + j];  in_ += P[800 + j];
                            hr += P[1200 + j]; hz += P[1600 + j]; hn += P[2000 + j];
                        }
                    }
                    float r = 1.f / (1.f + expf(-(ir + hr)));
                    float z = 1.f / (1.f + expf(-(iz + hz)));
                    float n = tanhf(in_ + r * hn);
                    hout[gb * Hsz + j] = (1.f - z) * n + z * hprev[gb * Hsz + j];
                }
                arrive_m(&g_sync[OFF_SUBH + (t + 1) * 8 * 64], gb >> 3, 8,
                         &g_sync[OFF_HROOT + t + 1], 8,
                         &g_sync[OFF_HFLAG + (t + 1) * 8 * 64]);
            }
        }
    } else {
        // ================= score pipeline (no backpressure on the chain) =================
        int fb = bx - GEMM_BLOCKS;

        // ---- duty 1: batch gi unit fb (t-ordered) ----
        if (tf && fb < 480) {
            float (*As)[68] = (float(*)[68])pool;
            float (*Ws)[44] = (float(*)[44])(pool + 3400);
            int bt = fb / 30;
            int jbase = (fb % 30) * 40;
            const float* A = g_xB + (size_t)bt * BH;
            int tj = tid / 8, tb = tid % 8;
            int b0 = 8 * tb, j0 = 4 * tj;
            bool active = (tj < 10);

            unsigned long long acc[4][4];
            #pragma unroll
            for (int j = 0; j < 4; j++)
                #pragma unroll
                for (int p = 0; p < 4; p++) acc[j][p] = 0ULL;

            for (int kt = 0; kt < 8; kt++) {
                int kbase = kt * KC;
                __syncthreads();
                for (int i = tid; i < 1600; i += 128) {
                    int q = i >> 6, b = i & 63;
                    float2 v = *(const float2*)&A[b * Hsz + kbase + 2 * q];
                    As[2 * q + 0][b] = v.x;
                    As[2 * q + 1][b] = v.y;
                }
                for (int i = tid; i < 1000; i += 128) {
                    int q = i / 40, j = i % 40;
                    float2 v = *(const float2*)&Wih[(size_t)(jbase + j) * Hsz + kbase + 2 * q];
                    Ws[2 * q + 0][j] = v.x;
                    Ws[2 * q + 1][j] = v.y;
                }
                __syncthreads();
                if (active) {
                    #pragma unroll 5
                    for (int k = 0; k < KC; k++) {
                        float4 av0 = *(const float4*)&As[k][b0];
                        float4 av1 = *(const float4*)&As[k][b0 + 4];
                        float4 wv  = *(const float4*)&Ws[k][j0];
                        unsigned long long a01 = pk2(av0.x, av0.y);
                        unsigned long long a23 = pk2(av0.z, av0.w);
                        unsigned long long a45 = pk2(av1.x, av1.y);
                        unsigned long long a67 = pk2(av1.z, av1.w);
                        unsigned long long w0 = pk2(wv.x, wv.x);
                        unsigned long long w1 = pk2(wv.y, wv.y);
                        unsigned long long w2 = pk2(wv.z, wv.z);
                        unsigned long long w3 = pk2(wv.w, wv.w);
                        ffma2(acc[0][0], a01, w0); ffma2(acc[0][1], a23, w0);
                        ffma2(acc[0][2], a45, w0); ffma2(acc[0][3], a67, w0);
                        ffma2(acc[1][0], a01, w1); ffma2(acc[1][1], a23, w1);
                        ffma2(acc[1][2], a45, w1); ffma2(acc[1][3], a67, w1);
                        ffma2(acc[2][0], a01, w2); ffma2(acc[2][1], a23, w2);
                        ffma2(acc[2][2], a45, w2); ffma2(acc[2][3], a67, w2);
                        ffma2(acc[3][0], a01, w3); ffma2(acc[3][1], a23, w3);
                        ffma2(acc[3][2], a45, w3); ffma2(acc[3][3], a67, w3);
                    }
                }
            }
            if (active) {
                #pragma unroll
                for (int p = 0; p < 4; p++) {
                    float2 f0 = up2(acc[0][p]);
                    float2 f1 = up2(acc[1][p]);
                    float2 f2 = up2(acc[2][p]);
                    float2 f3 = up2(acc[3][p]);
                    *(float4*)&g_giB[bt][b0 + 2 * p][jbase + j0]     = make_float4(f0.x, f1.x, f2.x, f3.x);
                    *(float4*)&g_giB[bt][b0 + 2 * p + 1][jbase + j0] = make_float4(f0.y, f1.y, f2.y, f3.y);
                }
            }
            __threadfence();
            __syncthreads();
            if (tid == 0) {
                int old = atomicAdd(&g_sync[OFF_BATCHCNT + bt], 1);
                if (old == 29) set_flags(&g_sync[OFF_BATCHFLAG + bt * 8 * 64]);
            }
            __syncthreads();
        }

        // ---- duty 2: transpose stripe ----
        {
            float (*tile)[33] = (float(*)[33])pool;
            int tx = tid & 31, ty = tid >> 5;    // 32 x 4
            for (int tt = fb; tt < Bsz * 16 * 13; tt += 512) {
                int b = tt / (16 * 13);
                int rem = tt % (16 * 13);
                int s0 = (rem / 13) * 32;
                int h0 = (rem % 13) * 32;
                __syncthreads();
                #pragma unroll
                for (int i = 0; i < 32; i += 4) {
                    int s = s0 + ty + i, h = h0 + tx;
                    if (h < Hsz) tile[ty + i][tx] = enc[((size_t)b * Ssz + s) * Hsz + h];
                }
                __syncthreads();
                #pragma unroll
                for (int i = 0; i < 32; i += 4) {
                    int h = h0 + ty + i, s = s0 + tx;
                    if (h < Hsz) g_encT[b][h][s] = tile[tx][ty + i];
                }
            }
        }
        arrive_m(&g_sync[OFF_TSUB], fb >> 4, 16, &g_sync[OFF_TROOT], 32,
                 &g_sync[OFF_TFLAG]);
        wait_flag_m(&g_sync[OFF_TFLAG], lane8);

        // ---- duty 3: score loop ----
        float* sh   = pool;
        float* redv = pool + 64;
        int*   redi = (int*)(pool + 192);
        float* flg  = pool + 320;

        int b  = fb >> 3;
        int hc = fb & 7;
        int len = lens[b];

        for (int t = 0; t < Lsz; t++) {
            wait_flag_m(&g_sync[OFF_HFLAG + (t + 1) * 8 * 64], lane8);

            const float* hnew = g_hHist[t + 1];
            if (tid < HCW)
                sh[tid] = hnew[b * Hsz + hc * HCW + tid];
            __syncthreads();

            int s0 = 4 * tid;
            if (s0 < len) {
                const float4* ep = (const float4*)&g_encT[b][hc * HCW][0] + tid;
                float4 acc = make_float4(0.f, 0.f, 0.f, 0.f);
                #pragma unroll 10
                for (int h = 0; h < HCW; h++) {
                    float hv = sh[h];
                    float4 e = ep[(size_t)h * 128];
                    acc.x += e.x * hv; acc.y += e.y * hv;
                    acc.z += e.z * hv; acc.w += e.w * hv;
                }
                *(float4*)&g_scpartL[t][hc][b][s0] = acc;
            }

            // zero this block's 1/8 of out row (b, t) before arrival
            {
                float* row = out + (size_t)b * Lsz * Vsz + (size_t)t * Vsz;
                float4* r4 = (float4*)row + hc * 1000;
                for (int i = tid; i < 1000; i += 128) {
                    asm volatile("st.global.cs.v4.f32 [%0], {%1, %2, %3, %4};"
                                 :: "l"(r4 + i), "f"(0.f), "f"(0.f), "f"(0.f), "f"(0.f) : "memory");
                }
            }

            __threadfence();
            __syncthreads();
            if (tid == 0) {
                int old = atomicAdd(&g_sync[OFF_CNTBT + t * Bsz + b], 1);
                flg[0] = (old == HC - 1) ? 1.f : 0.f;
            }
            __syncthreads();
            bool last = (flg[0] != 0.f);

            if (last) {
                __threadfence();
                float v[4];
                #pragma unroll
                for (int q = 0; q < 4; q++) {
                    int s = tid + 128 * q;
                    if (s < len) {
                        float sum = 0.f;
                        #pragma unroll
                        for (int p = 0; p < HC; p++) sum += g_scpartL[t][p][b][s];
                        v[q] = sum;
                    } else {
                        v[q] = -INFINITY;
                    }
                }
                float mv = v[0]; int mi = tid;
                #pragma unroll
                for (int q = 1; q < 4; q++)
                    if (v[q] > mv) { mv = v[q]; mi = tid + 128 * q; }
                redv[tid] = mv;
                redi[tid] = mi;
                __syncthreads();
                for (int st = 64; st > 0; st >>= 1) {
                    if (tid < st) {
                        float w2 = redv[tid + st];
                        int   i2 = redi[tid + st];
                        if (w2 > redv[tid] || (w2 == redv[tid] && i2 < redi[tid])) {
                            redv[tid] = w2;
                            redi[tid] = i2;
                        }
                    }
                    __syncthreads();
                }
                float m = redv[0];
                int amax = redi[0];
                __syncthreads();

                float e[4], lsum = 0.f;
                #pragma unroll
                for (int q = 0; q < 4; q++) {
                    e[q] = expf(v[q] - m);
                    lsum += e[q];
                }
                redv[tid] = lsum;
                __syncthreads();
                for (int st = 64; st > 0; st >>= 1) {
                    if (tid < st) redv[tid] += redv[tid + st];
                    __syncthreads();
                }
                float inv = 1.f / redv[0];

                float* orow = out + (size_t)b * Lsz * Vsz + (size_t)t * Vsz;
                #pragma unroll
                for (int q = 0; q < 4; q++) {
                    int s = tid + 128 * q;
                    if (s < len)
                        atomicAdd(&orow[uttrs[b * Ssz + s]], e[q] * inv);
                }

                if (tid == 0) {
                    int pred = uttrs[b * Ssz + amax];
                    if (write_preds)
                        out[(size_t)Bsz * Lsz * Vsz + (size_t)t * Bsz + b] = (float)pred;
                    ((int*)flg)[1] = tf ? targets[b * Lsz + t] : pred;
                }
                __syncthreads();
                if (!tf) {
                    int nxt = ((int*)flg)[1];
                    if (tid < 100)
                        ((float4*)(g_x + b * Hsz))[tid] =
                            ((const float4*)(emb + (size_t)nxt * Hsz))[tid];
                    __threadfence();
                    __syncthreads();
                    if (tid == 0) {
                        int old = atomicAdd(&g_sync[OFF_FUSEDCNT + t], 1);
                        if (old == Bsz - 1)
                            set_flags(&g_sync[OFF_FUSEDFLAG + t * 8 * 64]);
                    }
                }
            }
        }
    }
}

// ---------------- launch ----------------
extern "C" void kernel_launch(void* const* d_in, const int* in_sizes, int n_in,
                              void* d_out, int out_size) {
    const float* eh       = (const float*)d_in[0];
    const float* enc      = (const float*)d_in[1];
    const int*   lens     = (const int*)d_in[2];
    const int*   uttrs    = (const int*)d_in[3];
    const int*   targets  = (const int*)d_in[4];
    const int*   slot     = (const int*)d_in[5];
    const int*   use_tf   = (const int*)d_in[6];
    const float* emb      = (const float*)d_in[7];
    const float* slot_emb = (const float*)d_in[8];
    const float* Wih      = (const float*)d_in[9];
    const float* Whh      = (const float*)d_in[10];
    const float* bih      = (const float*)d_in[11];
    const float* bhh      = (const float*)d_in[12];
    float* out = (float*)d_out;

    int write_preds = out_size > Bsz * Lsz * Vsz;
    reset_kernel<<<1, 256>>>();
    persist_kernel<<<NBLK, 128>>>(eh, enc, lens, uttrs, targets, slot, use_tf,
                                  emb, slot_emb, Wih, Whh, bih, bhh,
                                  out, out_size, write_preds);
}